// round 2
// baseline (speedup 1.0000x reference)
#include <cuda_runtime.h>
#include <cstdint>

#define NB 2
#define NH 16
#define NS 2048
#define ND 64
#define TM 64
#define TN 64
#define NKT (NS / TN)
#define MWPR (NS / 32)            /* mask words per row = 64 */

// Static device scratch (allocation-free per harness rules).
__device__ unsigned g_mask[NB * NH * NS * MWPR];   // 16 MB: keep-bit mask, bit t%32 of word
__device__ float    g_vsum[NB * NH * NS * ND];     // 16 MB: v1 + v2

#define TF_ROUND(r) do { x0 += x1; x1 = __funnelshift_l(x1, x1, (r)); x1 ^= x0; } while (0)

// JAX partitionable threefry (default since jax 0.4.30):
// element i (row-major linear index) -> threefry2x32(key=(0,42), x0=hi32(i)=0, x1=lo32(i)=i),
// 32-bit sample = o0 ^ o1;  keep <=> bit31(o0^o1)==0  (uniform < 0.5).
// One thread per 32-bit mask word (32 evals).
__global__ void mask_kernel() {
    unsigned widx = blockIdx.x * blockDim.x + threadIdx.x;   // 0 .. 2^22-1
    const unsigned ks0 = 0u;
    const unsigned ks1 = 42u;
    const unsigned ks2 = ks0 ^ ks1 ^ 0x1BD11BDAu;
    unsigned m = 0u;
    const unsigned base = widx << 5;
#pragma unroll 8
    for (int k = 0; k < 32; ++k) {
        unsigned x0 = ks0;                    // hi32(i)=0 plus ks0
        unsigned x1 = (base + (unsigned)k) + ks1;
        TF_ROUND(13); TF_ROUND(15); TF_ROUND(26); TF_ROUND(6);
        x0 += ks1; x1 += ks2 + 1u;
        TF_ROUND(17); TF_ROUND(29); TF_ROUND(16); TF_ROUND(24);
        x0 += ks2; x1 += ks0 + 2u;
        TF_ROUND(13); TF_ROUND(15); TF_ROUND(26); TF_ROUND(6);
        x0 += ks0; x1 += ks1 + 3u;
        TF_ROUND(17); TF_ROUND(29); TF_ROUND(16); TF_ROUND(24);
        x0 += ks1; x1 += ks2 + 4u;
        TF_ROUND(13); TF_ROUND(15); TF_ROUND(26); TF_ROUND(6);
        x0 += ks2; x1 += ks0 + 5u;
        m |= ((~(x0 ^ x1)) >> 31) << k;       // keep bit
    }
    g_mask[widx] = m;
}

__global__ void vsum_kernel(const float4* __restrict__ v1, const float4* __restrict__ v2) {
    unsigned i = blockIdx.x * blockDim.x + threadIdx.x;  // exact grid, no bound check
    float4 a = v1[i], b = v2[i];
    float4 c;
    c.x = a.x + b.x; c.y = a.y + b.y; c.z = a.z + b.z; c.w = a.w + b.w;
    reinterpret_cast<float4*>(g_vsum)[i] = c;
}

// Flash-style attention. CTA = (q-tile of 64 rows, bh). 256 threads = 16x16,
// each thread owns a 4x4 score microtile and a 4(rows)x4(d) output microtile.
// Online softmax in exp2 domain. Denominator l is UNMASKED; numerator is masked.
__global__ __launch_bounds__(256) void attn_kernel(
    const float* __restrict__ q1, const float* __restrict__ q2,
    const float* __restrict__ k1g, const float* __restrict__ k2g,
    float* __restrict__ out)
{
    extern __shared__ float sm[];
    float* Qt1 = sm;                 // [d][row]  64x64
    float* Qt2 = Qt1 + TM * ND;
    float* Kt1 = Qt2 + TM * ND;      // [d][col]
    float* Kt2 = Kt1 + TN * ND;
    float* Vs  = Kt2 + TN * ND;      // [t][d]
    float* Ps  = Vs  + TN * ND;      // [row][t]

    const int tid = threadIdx.x;
    const int tx = tid & 15;
    const int ty = tid >> 4;
    const int qt = blockIdx.x;
    const int bh = blockIdx.y;

    const size_t bh_off = (size_t)bh * NS * ND;
    const float* q1b = q1  + bh_off + (size_t)qt * TM * ND;
    const float* q2b = q2  + bh_off + (size_t)qt * TM * ND;
    const float* k1b = k1g + bh_off;
    const float* k2b = k2g + bh_off;
    const float* vb  = g_vsum + bh_off;
    const unsigned* maskq = g_mask + ((size_t)bh * NS + (size_t)qt * TM) * MWPR;

    // Load Q tiles transposed: Qt[d][row]
#pragma unroll
    for (int it = 0; it < 4; ++it) {
        int e = tid + it * 256;          // 0..1023
        int row = e & 63;
        int dc  = e >> 6;                // 0..15
        float4 a = *(const float4*)&q1b[row * ND + dc * 4];
        float4 b = *(const float4*)&q2b[row * ND + dc * 4];
        Qt1[(dc * 4 + 0) * TM + row] = a.x;
        Qt1[(dc * 4 + 1) * TM + row] = a.y;
        Qt1[(dc * 4 + 2) * TM + row] = a.z;
        Qt1[(dc * 4 + 3) * TM + row] = a.w;
        Qt2[(dc * 4 + 0) * TM + row] = b.x;
        Qt2[(dc * 4 + 1) * TM + row] = b.y;
        Qt2[(dc * 4 + 2) * TM + row] = b.z;
        Qt2[(dc * 4 + 3) * TM + row] = b.w;
    }

    float m_run[4], l_run[4], acc[4][4];
#pragma unroll
    for (int i = 0; i < 4; ++i) {
        m_run[i] = -1e30f;
        l_run[i] = 0.f;
#pragma unroll
        for (int c = 0; c < 4; ++c) acc[i][c] = 0.f;
    }

    // fold 1/sqrt(64) and log2(e) so softmax runs in exp2 domain
    const float SCL = 0.125f * 1.44269504088896340736f;

    for (int kt = 0; kt < NKT; ++kt) {
        __syncthreads();  // prior iteration done reading Kt/Vs/Ps
#pragma unroll
        for (int it = 0; it < 4; ++it) {
            int e = tid + it * 256;
            int row = e & 63;
            int dc  = e >> 6;
            size_t goff = (size_t)(kt * TN + row) * ND + dc * 4;
            float4 a = *(const float4*)&k1b[goff];
            float4 b = *(const float4*)&k2b[goff];
            float4 v = *(const float4*)&vb[goff];
            Kt1[(dc * 4 + 0) * TN + row] = a.x;
            Kt1[(dc * 4 + 1) * TN + row] = a.y;
            Kt1[(dc * 4 + 2) * TN + row] = a.z;
            Kt1[(dc * 4 + 3) * TN + row] = a.w;
            Kt2[(dc * 4 + 0) * TN + row] = b.x;
            Kt2[(dc * 4 + 1) * TN + row] = b.y;
            Kt2[(dc * 4 + 2) * TN + row] = b.z;
            Kt2[(dc * 4 + 3) * TN + row] = b.w;
            *(float4*)&Vs[row * ND + dc * 4] = v;
        }
        __syncthreads();

        // dual-source score microtile
        float s[4][4];
#pragma unroll
        for (int i = 0; i < 4; ++i)
#pragma unroll
            for (int j = 0; j < 4; ++j) s[i][j] = 0.f;

#pragma unroll 4
        for (int kk = 0; kk < ND; ++kk) {
            float4 A1 = *(const float4*)&Qt1[kk * TM + ty * 4];
            float4 A2 = *(const float4*)&Qt2[kk * TM + ty * 4];
            float4 B1 = *(const float4*)&Kt1[kk * TN + tx * 4];
            float4 B2 = *(const float4*)&Kt2[kk * TN + tx * 4];
            const float* a1 = (const float*)&A1;
            const float* a2 = (const float*)&A2;
            const float* b1 = (const float*)&B1;
            const float* b2 = (const float*)&B2;
#pragma unroll
            for (int i = 0; i < 4; ++i)
#pragma unroll
                for (int j = 0; j < 4; ++j) {
                    s[i][j] = fmaf(a1[i], b1[j], s[i][j]);
                    s[i][j] = fmaf(a2[i], b2[j], s[i][j]);
                }
        }
#pragma unroll
        for (int i = 0; i < 4; ++i)
#pragma unroll
            for (int j = 0; j < 4; ++j) s[i][j] *= SCL;

        // online softmax stats (row groups = 16 lanes sharing ty)
        float mn[4], al[4], rs[4];
#pragma unroll
        for (int i = 0; i < 4; ++i) {
            float t = fmaxf(fmaxf(s[i][0], s[i][1]), fmaxf(s[i][2], s[i][3]));
            t = fmaxf(t, __shfl_xor_sync(0xffffffffu, t, 1, 16));
            t = fmaxf(t, __shfl_xor_sync(0xffffffffu, t, 2, 16));
            t = fmaxf(t, __shfl_xor_sync(0xffffffffu, t, 4, 16));
            t = fmaxf(t, __shfl_xor_sync(0xffffffffu, t, 8, 16));
            mn[i] = fmaxf(m_run[i], t);
            al[i] = exp2f(m_run[i] - mn[i]);
            m_run[i] = mn[i];
        }
#pragma unroll
        for (int i = 0; i < 4; ++i) {
            rs[i] = 0.f;
#pragma unroll
            for (int j = 0; j < 4; ++j) {
                float e = exp2f(s[i][j] - mn[i]);
                s[i][j] = e;
                rs[i] += e;
            }
        }
#pragma unroll
        for (int i = 0; i < 4; ++i) {
            float r = rs[i];
            r += __shfl_xor_sync(0xffffffffu, r, 1, 16);
            r += __shfl_xor_sync(0xffffffffu, r, 2, 16);
            r += __shfl_xor_sync(0xffffffffu, r, 4, 16);
            r += __shfl_xor_sync(0xffffffffu, r, 8, 16);
            l_run[i] = l_run[i] * al[i] + r;   // UNMASKED denominator
#pragma unroll
            for (int c = 0; c < 4; ++c) acc[i][c] *= al[i];
        }

        // apply dropout mask to the numerator, stage P in smem
        const int wcol = kt * 2 + (tx >> 3);       // word index within row
        const int sh   = (tx & 7) * 4;             // bit offset of this thread's 4 cols
#pragma unroll
        for (int i = 0; i < 4; ++i) {
            unsigned w  = maskq[(ty * 4 + i) * MWPR + wcol];
            unsigned b4 = (w >> sh) & 0xFu;
            float4 pv;
            pv.x = (b4 & 1u) ? s[i][0] : 0.f;
            pv.y = (b4 & 2u) ? s[i][1] : 0.f;
            pv.z = (b4 & 4u) ? s[i][2] : 0.f;
            pv.w = (b4 & 8u) ? s[i][3] : 0.f;
            *(float4*)&Ps[(ty * 4 + i) * TN + tx * 4] = pv;
        }
        __syncthreads();

        // PV GEMM: acc[row][d] += P[row][t] * Vsum[t][d]
#pragma unroll 4
        for (int tt = 0; tt < TN; ++tt) {
            float4 V4 = *(const float4*)&Vs[tt * ND + tx * 4];
            const float* vv = (const float*)&V4;
            float p0 = Ps[(ty * 4 + 0) * TN + tt];
            float p1 = Ps[(ty * 4 + 1) * TN + tt];
            float p2 = Ps[(ty * 4 + 2) * TN + tt];
            float p3 = Ps[(ty * 4 + 3) * TN + tt];
#pragma unroll
            for (int c = 0; c < 4; ++c) {
                acc[0][c] = fmaf(p0, vv[c], acc[0][c]);
                acc[1][c] = fmaf(p1, vv[c], acc[1][c]);
                acc[2][c] = fmaf(p2, vv[c], acc[2][c]);
                acc[3][c] = fmaf(p3, vv[c], acc[3][c]);
            }
        }
    }

    // epilogue: out = 2 * acc / l   (1/(1-p) = 2 inverted-dropout scaling)
    float* ob = out + bh_off + (size_t)qt * TM * ND;
#pragma unroll
    for (int i = 0; i < 4; ++i) {
        float inv = 2.0f / l_run[i];
        float4 o;
        o.x = acc[i][0] * inv;
        o.y = acc[i][1] * inv;
        o.z = acc[i][2] * inv;
        o.w = acc[i][3] * inv;
        *(float4*)&ob[(ty * 4 + i) * ND + tx * 4] = o;
    }
}

extern "C" void kernel_launch(void* const* d_in, const int* in_sizes, int n_in,
                              void* d_out, int out_size) {
    const float* q1 = (const float*)d_in[0];
    const float* q2 = (const float*)d_in[1];
    const float* k1 = (const float*)d_in[2];
    const float* k2 = (const float*)d_in[3];
    const float* v1 = (const float*)d_in[4];
    const float* v2 = (const float*)d_in[5];
    float* out = (float*)d_out;

    // 1) dropout mask (partitionable threefry, one thread per 32-bit word)
    mask_kernel<<<(NB * NH * NS * MWPR) / 256, 256>>>();
    // 2) vsum = v1 + v2
    vsum_kernel<<<(NB * NH * NS * ND / 4) / 256, 256>>>((const float4*)v1, (const float4*)v2);
    // 3) flash attention
    const int smem = 6 * TM * ND * (int)sizeof(float);  // 96 KB
    cudaFuncSetAttribute(attn_kernel, cudaFuncAttributeMaxDynamicSharedMemorySize, smem);
    dim3 grid(NS / TM, NB * NH);
    attn_kernel<<<grid, 256, smem>>>(q1, q2, k1, k2, out);
}

// round 4
// speedup vs baseline: 2.4072x; 2.4072x over previous
#include <cuda_runtime.h>
#include <cstdint>

#define NB 2
#define NH 16
#define NS 2048
#define ND 64
#define TQ 64
#define TK 64
#define NKT (NS / TK)          /* 32 k-tiles */
#define MWPR (NS / 32)         /* mask words per row = 64 */
#define KW 36                  /* smem row stride in u32 words (144B, 16B-aligned, conflict-free frags) */

// ---------------- static device scratch ----------------
__device__ unsigned g_mask[NB * NH * NS * MWPR];        // 16 MB keep-bit mask
__device__ unsigned g_vth[NB * NH * ND * (NS / 2)];     // V^T hi bf16x2 [bh][d][t/2]
__device__ unsigned g_vtl[NB * NH * ND * (NS / 2)];     // V^T lo bf16x2

// ---------------- helpers ----------------
__device__ __forceinline__ float ex2f(float x) {
    float r; asm("ex2.approx.ftz.f32 %0, %1;" : "=f"(r) : "f"(x)); return r;
}
// pack two fp32 -> bf16x2 (lo half = a, hi half = b), round-to-nearest
__device__ __forceinline__ uint32_t packbf(float a, float b) {
    uint32_t r; asm("cvt.rn.bf16x2.f32 %0, %1, %2;" : "=r"(r) : "f"(b), "f"(a)); return r;
}
__device__ __forceinline__ float bf_lo_f(uint32_t p) { return __uint_as_float(p << 16); }
__device__ __forceinline__ float bf_hi_f(uint32_t p) { return __uint_as_float(p & 0xffff0000u); }

__device__ __forceinline__ void mma_bf16(float c[4],
    uint32_t a0, uint32_t a1, uint32_t a2, uint32_t a3, uint32_t b0, uint32_t b1) {
    asm volatile("mma.sync.aligned.m16n8k16.row.col.f32.bf16.bf16.f32 "
        "{%0,%1,%2,%3}, {%4,%5,%6,%7}, {%8,%9}, {%0,%1,%2,%3};"
        : "+f"(c[0]), "+f"(c[1]), "+f"(c[2]), "+f"(c[3])
        : "r"(a0), "r"(a1), "r"(a2), "r"(a3), "r"(b0), "r"(b1));
}

// ---------------- mask kernel (validated round 2) ----------------
#define TF_ROUND(r) do { x0 += x1; x1 = __funnelshift_l(x1, x1, (r)); x1 ^= x0; } while (0)
__global__ void mask_kernel() {
    unsigned widx = blockIdx.x * blockDim.x + threadIdx.x;
    const unsigned ks0 = 0u, ks1 = 42u;
    const unsigned ks2 = ks0 ^ ks1 ^ 0x1BD11BDAu;
    unsigned m = 0u;
    const unsigned base = widx << 5;
#pragma unroll 8
    for (int k = 0; k < 32; ++k) {
        unsigned x0 = ks0;
        unsigned x1 = (base + (unsigned)k) + ks1;
        TF_ROUND(13); TF_ROUND(15); TF_ROUND(26); TF_ROUND(6);
        x0 += ks1; x1 += ks2 + 1u;
        TF_ROUND(17); TF_ROUND(29); TF_ROUND(16); TF_ROUND(24);
        x0 += ks2; x1 += ks0 + 2u;
        TF_ROUND(13); TF_ROUND(15); TF_ROUND(26); TF_ROUND(6);
        x0 += ks0; x1 += ks1 + 3u;
        TF_ROUND(17); TF_ROUND(29); TF_ROUND(16); TF_ROUND(24);
        x0 += ks1; x1 += ks2 + 4u;
        TF_ROUND(13); TF_ROUND(15); TF_ROUND(26); TF_ROUND(6);
        x0 += ks2; x1 += ks0 + 5u;
        m |= ((~(x0 ^ x1)) >> 31) << k;
    }
    g_mask[widx] = m;
}

// ---------------- V^T prep: (v1+v2) -> bf16 hi/lo, transposed [bh][d][t] ----------------
__global__ __launch_bounds__(256) void vtrans_kernel(const float* __restrict__ v1,
                                                     const float* __restrict__ v2) {
    __shared__ float ts[64 * 65];
    const int tb = blockIdx.x;      // t-tile (64 rows of t)
    const int bh = blockIdx.y;
    const int tid = threadIdx.x;
    const float* p1 = v1 + ((size_t)bh * NS + tb * 64) * ND;
    const float* p2 = v2 + ((size_t)bh * NS + tb * 64) * ND;
#pragma unroll
    for (int i = 0; i < 4; ++i) {
        int e = tid + i * 256;           // 1024 float4
        int r = e >> 4, c4 = e & 15;
        float4 a = *(const float4*)&p1[r * ND + c4 * 4];
        float4 b = *(const float4*)&p2[r * ND + c4 * 4];
        ts[r * 65 + c4 * 4 + 0] = a.x + b.x;
        ts[r * 65 + c4 * 4 + 1] = a.y + b.y;
        ts[r * 65 + c4 * 4 + 2] = a.z + b.z;
        ts[r * 65 + c4 * 4 + 3] = a.w + b.w;
    }
    __syncthreads();
#pragma unroll
    for (int i = 0; i < 8; ++i) {
        int e = tid + i * 256;           // 2048 outputs (u32 = t-pair)
        int d = e >> 5, tp = e & 31;
        float x = ts[(2 * tp) * 65 + d];
        float y = ts[(2 * tp + 1) * 65 + d];
        uint32_t h = packbf(x, y);
        uint32_t l = packbf(x - bf_lo_f(h), y - bf_hi_f(h));
        size_t o = ((size_t)bh * 64 + d) * (NS / 2) + tb * 32 + tp;
        g_vth[o] = h;
        g_vtl[o] = l;
    }
}

// ---------------- FA2-style mma.sync attention ----------------
// CTA: 64 q-rows x full S. 128 threads = 4 warps, warp w owns rows [w*16, w*16+16).
// Per k-tile (64 keys): stage K1h/K1l/K2h/K2l and V^T h/l in smem, mma QK (6 passes),
// exp2 + mask in C-regs, repack into A-frags, mma PV (3 passes).
__global__ void __launch_bounds__(128, 2) attn_kernel(
    const float* __restrict__ q1, const float* __restrict__ q2,
    const float* __restrict__ k1g, const float* __restrict__ k2g,
    float* __restrict__ out)
{
    extern __shared__ uint32_t smw[];
    uint32_t* sK = smw;                    // [4][64][KW]  k1h,k1l,k2h,k2l
    uint32_t* sV = smw + 4 * 64 * KW;      // [2][64][KW]  vth, vtl  (rows = d)

    const int tid  = threadIdx.x;
    const int warp = tid >> 5, lane = tid & 31;
    const int gid  = lane >> 2, tg = lane & 3;
    const int qt = blockIdx.x, bh = blockIdx.y;
    const size_t bh_off = (size_t)bh * NS * ND;
    const int m_loc = warp * 16 + gid;     // q row within CTA tile (pairs with m_loc+8)

    // ---- stage Q (fp32 -> bf16 hi/lo) into sK area, then load A-fragments ----
    {
        const float* qs[2] = { q1 + bh_off + (size_t)qt * TQ * ND,
                               q2 + bh_off + (size_t)qt * TQ * ND };
#pragma unroll
        for (int s = 0; s < 2; ++s) {
            uint32_t* dh = sK + (2 * s + 0) * 64 * KW;
            uint32_t* dl = sK + (2 * s + 1) * 64 * KW;
#pragma unroll
            for (int i = 0; i < 8; ++i) {
                int e = i * 128 + tid;
                int r = e >> 4, c4 = e & 15;
                float4 v = *(const float4*)&qs[s][(size_t)r * ND + c4 * 4];
                uint32_t h0 = packbf(v.x, v.y), h1 = packbf(v.z, v.w);
                uint32_t w0 = packbf(v.x - bf_lo_f(h0), v.y - bf_hi_f(h0));
                uint32_t w1 = packbf(v.z - bf_lo_f(h1), v.w - bf_hi_f(h1));
                dh[r * KW + c4 * 2]     = h0;
                dh[r * KW + c4 * 2 + 1] = h1;
                dl[r * KW + c4 * 2]     = w0;
                dl[r * KW + c4 * 2 + 1] = w1;
            }
        }
    }
    __syncthreads();
    uint32_t qa[4][4][4];   // [arr: q1h,q1l,q2h,q2l][kstep][reg]
#pragma unroll
    for (int a = 0; a < 4; ++a) {
        const uint32_t* base = sK + a * 64 * KW;
#pragma unroll
        for (int s = 0; s < 4; ++s) {
            int w = tg + 8 * s;
            qa[a][s][0] = base[(m_loc)     * KW + w];
            qa[a][s][1] = base[(m_loc + 8) * KW + w];
            qa[a][s][2] = base[(m_loc)     * KW + w + 4];
            qa[a][s][3] = base[(m_loc + 8) * KW + w + 4];
        }
    }

    float o[8][4];
#pragma unroll
    for (int j = 0; j < 8; ++j) { o[j][0] = o[j][1] = o[j][2] = o[j][3] = 0.f; }
    float lr0 = 0.f, lr1 = 0.f;
    const float SCL2 = 0.18033688f;   // log2(e)/8

    const unsigned* mrow0 = g_mask + ((size_t)bh * NS + (size_t)qt * TQ + m_loc) * MWPR;
    const unsigned* mrow1 = mrow0 + 8 * MWPR;

    for (int kt = 0; kt < NKT; ++kt) {
        __syncthreads();   // previous tile's smem reads done
        // ---- load K tile (fp32 -> bf16 hi/lo) ----
        {
            const float* ks[2] = { k1g + bh_off + (size_t)kt * TK * ND,
                                   k2g + bh_off + (size_t)kt * TK * ND };
#pragma unroll
            for (int s = 0; s < 2; ++s) {
                uint32_t* dh = sK + (2 * s + 0) * 64 * KW;
                uint32_t* dl = sK + (2 * s + 1) * 64 * KW;
#pragma unroll
                for (int i = 0; i < 8; ++i) {
                    int e = i * 128 + tid;
                    int r = e >> 4, c4 = e & 15;
                    float4 v = *(const float4*)&ks[s][(size_t)r * ND + c4 * 4];
                    uint32_t h0 = packbf(v.x, v.y), h1 = packbf(v.z, v.w);
                    uint32_t w0 = packbf(v.x - bf_lo_f(h0), v.y - bf_hi_f(h0));
                    uint32_t w1 = packbf(v.z - bf_lo_f(h1), v.w - bf_hi_f(h1));
                    dh[r * KW + c4 * 2]     = h0;
                    dh[r * KW + c4 * 2 + 1] = h1;
                    dl[r * KW + c4 * 2]     = w0;
                    dl[r * KW + c4 * 2 + 1] = w1;
                }
            }
            // ---- load V^T tile (already bf16 pairs) ----
            const size_t rowbase = (size_t)bh * ND * (NS / 2);
#pragma unroll
            for (int i = 0; i < 4; ++i) {
                int e = i * 128 + tid;            // 512 uint4 per array
                int d = e >> 3, wc = (e & 7) * 4;
                size_t gi = rowbase + (size_t)d * (NS / 2) + kt * 32 + wc;
                uint4 hv = *(const uint4*)&g_vth[gi];
                uint4 lv = *(const uint4*)&g_vtl[gi];
                *(uint4*)&sV[d * KW + wc] = hv;
                *(uint4*)&sV[64 * KW + d * KW + wc] = lv;
            }
        }
        __syncthreads();

        // ---- QK: 6 split passes into fp32 C ----
        float c[8][4];
#pragma unroll
        for (int j = 0; j < 8; ++j) { c[j][0] = c[j][1] = c[j][2] = c[j][3] = 0.f; }
#pragma unroll
        for (int j = 0; j < 8; ++j) {
            const int row = j * 8 + gid;
#pragma unroll
            for (int s = 0; s < 4; ++s) {
                const int w = tg + 8 * s;
                uint32_t b1h0 = sK[0 * 64 * KW + row * KW + w], b1h1 = sK[0 * 64 * KW + row * KW + w + 4];
                uint32_t b1l0 = sK[1 * 64 * KW + row * KW + w], b1l1 = sK[1 * 64 * KW + row * KW + w + 4];
                uint32_t b2h0 = sK[2 * 64 * KW + row * KW + w], b2h1 = sK[2 * 64 * KW + row * KW + w + 4];
                uint32_t b2l0 = sK[3 * 64 * KW + row * KW + w], b2l1 = sK[3 * 64 * KW + row * KW + w + 4];
                mma_bf16(c[j], qa[0][s][0], qa[0][s][1], qa[0][s][2], qa[0][s][3], b1h0, b1h1);
                mma_bf16(c[j], qa[0][s][0], qa[0][s][1], qa[0][s][2], qa[0][s][3], b1l0, b1l1);
                mma_bf16(c[j], qa[1][s][0], qa[1][s][1], qa[1][s][2], qa[1][s][3], b1h0, b1h1);
                mma_bf16(c[j], qa[2][s][0], qa[2][s][1], qa[2][s][2], qa[2][s][3], b2h0, b2h1);
                mma_bf16(c[j], qa[2][s][0], qa[2][s][1], qa[2][s][2], qa[2][s][3], b2l0, b2l1);
                mma_bf16(c[j], qa[3][s][0], qa[3][s][1], qa[3][s][2], qa[3][s][3], b2h0, b2h1);
            }
        }

        // ---- exp2 + l accumulation (unmasked) + dropout mask (numerator only) ----
        const unsigned mw00 = mrow0[kt * 2], mw01 = mrow0[kt * 2 + 1];
        const unsigned mw10 = mrow1[kt * 2], mw11 = mrow1[kt * 2 + 1];
#pragma unroll
        for (int j = 0; j < 8; ++j) {
            const int sh = ((j & 3) * 8) + tg * 2;
            const unsigned wm  = (j < 4) ? mw00 : mw01;
            const unsigned wm8 = (j < 4) ? mw10 : mw11;
            float p0 = ex2f(c[j][0] * SCL2), p1 = ex2f(c[j][1] * SCL2);
            float p2 = ex2f(c[j][2] * SCL2), p3 = ex2f(c[j][3] * SCL2);
            lr0 += p0 + p1;
            lr1 += p2 + p3;
            c[j][0] = ((wm  >> sh)       & 1u) ? p0 : 0.f;
            c[j][1] = ((wm  >> (sh + 1)) & 1u) ? p1 : 0.f;
            c[j][2] = ((wm8 >> sh)       & 1u) ? p2 : 0.f;
            c[j][3] = ((wm8 >> (sh + 1)) & 1u) ? p3 : 0.f;
        }

        // ---- PV: repack C -> A-frags (hi/lo), 3 split passes ----
#pragma unroll
        for (int s = 0; s < 4; ++s) {
            uint32_t ph[4], pl[4];
            {
                float x, y;
                x = c[2 * s][0];     y = c[2 * s][1];
                ph[0] = packbf(x, y); pl[0] = packbf(x - bf_lo_f(ph[0]), y - bf_hi_f(ph[0]));
                x = c[2 * s][2];     y = c[2 * s][3];
                ph[1] = packbf(x, y); pl[1] = packbf(x - bf_lo_f(ph[1]), y - bf_hi_f(ph[1]));
                x = c[2 * s + 1][0]; y = c[2 * s + 1][1];
                ph[2] = packbf(x, y); pl[2] = packbf(x - bf_lo_f(ph[2]), y - bf_hi_f(ph[2]));
                x = c[2 * s + 1][2]; y = c[2 * s + 1][3];
                ph[3] = packbf(x, y); pl[3] = packbf(x - bf_lo_f(ph[3]), y - bf_hi_f(ph[3]));
            }
#pragma unroll
            for (int j = 0; j < 8; ++j) {
                const int row = j * 8 + gid;
                const int w = tg + 8 * s;
                uint32_t vh0 = sV[row * KW + w],           vh1 = sV[row * KW + w + 4];
                uint32_t vl0 = sV[64 * KW + row * KW + w], vl1 = sV[64 * KW + row * KW + w + 4];
                mma_bf16(o[j], ph[0], ph[1], ph[2], ph[3], vh0, vh1);
                mma_bf16(o[j], ph[0], ph[1], ph[2], ph[3], vl0, vl1);
                mma_bf16(o[j], pl[0], pl[1], pl[2], pl[3], vh0, vh1);
            }
        }
    }

    // ---- reduce l within quad (4 lanes share a row), normalize, store ----
    lr0 += __shfl_xor_sync(0xffffffffu, lr0, 1);
    lr0 += __shfl_xor_sync(0xffffffffu, lr0, 2);
    lr1 += __shfl_xor_sync(0xffffffffu, lr1, 1);
    lr1 += __shfl_xor_sync(0xffffffffu, lr1, 2);
    const float inv0 = 2.0f / lr0;     // 1/(1-p) = 2 inverted-dropout scaling
    const float inv1 = 2.0f / lr1;

    float* ob = out + bh_off + (size_t)(qt * TQ + m_loc) * ND;
#pragma unroll
    for (int j = 0; j < 8; ++j) {
        const int d = j * 8 + tg * 2;
        *(float2*)&ob[d]           = make_float2(o[j][0] * inv0, o[j][1] * inv0);
        *(float2*)&ob[8 * ND + d]  = make_float2(o[j][2] * inv1, o[j][3] * inv1);
    }
}

extern "C" void kernel_launch(void* const* d_in, const int* in_sizes, int n_in,
                              void* d_out, int out_size) {
    const float* q1 = (const float*)d_in[0];
    const float* q2 = (const float*)d_in[1];
    const float* k1 = (const float*)d_in[2];
    const float* k2 = (const float*)d_in[3];
    const float* v1 = (const float*)d_in[4];
    const float* v2 = (const float*)d_in[5];
    float* out = (float*)d_out;

    mask_kernel<<<(NB * NH * NS * MWPR) / 256, 256>>>();
    vtrans_kernel<<<dim3(NS / 64, NB * NH), 256>>>(v1, v2);
    const int smem = 6 * 64 * KW * (int)sizeof(uint32_t);   // 55296 B
    cudaFuncSetAttribute(attn_kernel, cudaFuncAttributeMaxDynamicSharedMemorySize, smem);
    attn_kernel<<<dim3(NS / TQ, NB * NH), 128, smem>>>(q1, q2, k1, k2, out);
}

// round 5
// speedup vs baseline: 2.4256x; 1.0076x over previous
#include <cuda_runtime.h>
#include <cstdint>

#define NB 2
#define NH 16
#define NS 2048
#define ND 64
#define TQ 128
#define TK 64
#define NKT (NS / TK)          /* 32 k-tiles */
#define MWPR (NS / 32)         /* mask words per row = 64 */
#define KW 36                  /* smem row stride in u32 words */
#define ABUF (64 * KW)         /* words per array tile = 2304 */
#define BUFW (6 * ABUF)        /* words per pipeline buffer = 13824 */

// ---------------- static device scratch ----------------
__device__ unsigned g_k1h[32 * 2048 * 32];   // K bf16 hi/lo, d-pair words [bh][t][d/2]
__device__ unsigned g_k1l[32 * 2048 * 32];
__device__ unsigned g_k2h[32 * 2048 * 32];
__device__ unsigned g_k2l[32 * 2048 * 32];
__device__ unsigned g_vth[32 * 64 * 1024];   // V^T hi bf16x2 [bh][d][t/2]
__device__ unsigned g_vtl[32 * 64 * 1024];

// ---------------- helpers ----------------
__device__ __forceinline__ uint32_t smem_u32(const void* p) {
    uint32_t a;
    asm("{ .reg .u64 t; cvta.to.shared.u64 t, %1; cvt.u32.u64 %0, t; }" : "=r"(a) : "l"(p));
    return a;
}
__device__ __forceinline__ float ex2f(float x) {
    float r; asm("ex2.approx.ftz.f32 %0, %1;" : "=f"(r) : "f"(x)); return r;
}
__device__ __forceinline__ uint32_t packbf(float a, float b) {
    uint32_t r; asm("cvt.rn.bf16x2.f32 %0, %1, %2;" : "=r"(r) : "f"(b), "f"(a)); return r;
}
__device__ __forceinline__ float bf_lo_f(uint32_t p) { return __uint_as_float(p << 16); }
__device__ __forceinline__ float bf_hi_f(uint32_t p) { return __uint_as_float(p & 0xffff0000u); }

__device__ __forceinline__ void mma_bf16(float c[4],
    uint32_t a0, uint32_t a1, uint32_t a2, uint32_t a3, uint32_t b0, uint32_t b1) {
    asm volatile("mma.sync.aligned.m16n8k16.row.col.f32.bf16.bf16.f32 "
        "{%0,%1,%2,%3}, {%4,%5,%6,%7}, {%8,%9}, {%0,%1,%2,%3};"
        : "+f"(c[0]), "+f"(c[1]), "+f"(c[2]), "+f"(c[3])
        : "r"(a0), "r"(a1), "r"(a2), "r"(a3), "r"(b0), "r"(b1));
}

#define CP16(dst, src) \
    asm volatile("cp.async.cg.shared.global [%0], [%1], 16;" :: "r"(dst), "l"(src))
#define CP_COMMIT() asm volatile("cp.async.commit_group;" ::: "memory")

// threefry2x32-20, key (0,42): element i -> (x0=0, x1=i); sample = o0^o1; keep<=>bit31==0
#define TF_ROUND(r) do { x0 += x1; x1 = __funnelshift_l(x1, x1, (r)); x1 ^= x0; } while (0)
__device__ __forceinline__ unsigned tf_word(unsigned widx) {
    const unsigned ks1 = 42u;
    const unsigned ks2 = 42u ^ 0x1BD11BDAu;
    unsigned m = 0u;
    const unsigned base = widx << 5;
#pragma unroll 4
    for (int k = 0; k < 32; ++k) {
        unsigned x0 = 0u;
        unsigned x1 = (base + (unsigned)k) + ks1;
        TF_ROUND(13); TF_ROUND(15); TF_ROUND(26); TF_ROUND(6);
        x0 += ks1; x1 += ks2 + 1u;
        TF_ROUND(17); TF_ROUND(29); TF_ROUND(16); TF_ROUND(24);
        x0 += ks2; x1 += 0u + 2u;
        TF_ROUND(13); TF_ROUND(15); TF_ROUND(26); TF_ROUND(6);
        x0 += 0u; x1 += ks1 + 3u;
        TF_ROUND(17); TF_ROUND(29); TF_ROUND(16); TF_ROUND(24);
        x0 += ks1; x1 += ks2 + 4u;
        TF_ROUND(13); TF_ROUND(15); TF_ROUND(26); TF_ROUND(6);
        x0 += ks2; x1 += 0u + 5u;
        m |= ((~(x0 ^ x1)) >> 31) << k;
    }
    return m;
}

// ---------------- K prep: fp32 -> bf16 hi/lo global ----------------
__global__ __launch_bounds__(256) void kprep_kernel(const float4* __restrict__ k1,
                                                    const float4* __restrict__ k2) {
    unsigned i = blockIdx.x * 256 + threadIdx.x;      // 0 .. 2^20-1 float4 per array
    const float4* src = blockIdx.y ? k2 : k1;
    unsigned* dh = blockIdx.y ? g_k2h : g_k1h;
    unsigned* dl = blockIdx.y ? g_k2l : g_k1l;
    float4 v = src[i];
    uint32_t h0 = packbf(v.x, v.y), h1 = packbf(v.z, v.w);
    uint32_t l0 = packbf(v.x - bf_lo_f(h0), v.y - bf_hi_f(h0));
    uint32_t l1 = packbf(v.z - bf_lo_f(h1), v.w - bf_hi_f(h1));
    *(uint2*)&dh[i * 2] = make_uint2(h0, h1);
    *(uint2*)&dl[i * 2] = make_uint2(l0, l1);
}

// ---------------- V^T prep (validated round 4) ----------------
__global__ __launch_bounds__(256) void vtrans_kernel(const float* __restrict__ v1,
                                                     const float* __restrict__ v2) {
    __shared__ float ts[64 * 65];
    const int tb = blockIdx.x;
    const int bh = blockIdx.y;
    const int tid = threadIdx.x;
    const float* p1 = v1 + ((size_t)bh * NS + tb * 64) * ND;
    const float* p2 = v2 + ((size_t)bh * NS + tb * 64) * ND;
#pragma unroll
    for (int i = 0; i < 4; ++i) {
        int e = tid + i * 256;
        int r = e >> 4, c4 = e & 15;
        float4 a = *(const float4*)&p1[r * ND + c4 * 4];
        float4 b = *(const float4*)&p2[r * ND + c4 * 4];
        ts[r * 65 + c4 * 4 + 0] = a.x + b.x;
        ts[r * 65 + c4 * 4 + 1] = a.y + b.y;
        ts[r * 65 + c4 * 4 + 2] = a.z + b.z;
        ts[r * 65 + c4 * 4 + 3] = a.w + b.w;
    }
    __syncthreads();
#pragma unroll
    for (int i = 0; i < 8; ++i) {
        int e = tid + i * 256;
        int d = e >> 5, tp = e & 31;
        float x = ts[(2 * tp) * 65 + d];
        float y = ts[(2 * tp + 1) * 65 + d];
        uint32_t h = packbf(x, y);
        uint32_t l = packbf(x - bf_lo_f(h), y - bf_hi_f(h));
        size_t o = ((size_t)bh * 64 + d) * (NS / 2) + tb * 32 + tp;
        g_vth[o] = h;
        g_vtl[o] = l;
    }
}

// ---------------- fused attention + threefry ----------------
// CTA: 128 q-rows, 256 threads (8 warps, warp w owns rows [w*16, w*16+16)).
// Per k-tile: cp.async prefetch next tile; compute this tile's 256 mask words
// (threefry, ALU pipe) overlapping QK mma (tensor pipe); exp2+mask epilogue; PV mma.
__global__ void __launch_bounds__(256, 1) attn_kernel(
    const float* __restrict__ q1, const float* __restrict__ q2,
    float* __restrict__ out)
{
    extern __shared__ uint32_t smw[];
    uint32_t* smask = smw + 2 * BUFW;
    const uint32_t sb = smem_u32(smw);

    const int tid  = threadIdx.x;
    const int warp = tid >> 5, lane = tid & 31;
    const int gid  = lane >> 2, tg = lane & 3;
    const int qt = blockIdx.x, bh = blockIdx.y;
    const size_t bh_off = (size_t)bh * NS * ND;
    const int m_loc = warp * 16 + gid;

    // ---- stage Q (fp32 -> bf16 hi/lo) into smem, read A-fragments ----
    {
        const float* qs[2] = { q1 + bh_off + (size_t)qt * TQ * ND,
                               q2 + bh_off + (size_t)qt * TQ * ND };
#pragma unroll
        for (int s = 0; s < 2; ++s) {
            uint32_t* dh = smw + (2 * s + 0) * (128 * KW);
            uint32_t* dl = smw + (2 * s + 1) * (128 * KW);
#pragma unroll
            for (int i = 0; i < 8; ++i) {
                int e = i * 256 + tid;           // 0..2047
                int r = e >> 4, c4 = e & 15;
                float4 v = *(const float4*)&qs[s][(size_t)r * ND + c4 * 4];
                uint32_t h0 = packbf(v.x, v.y), h1 = packbf(v.z, v.w);
                uint32_t w0 = packbf(v.x - bf_lo_f(h0), v.y - bf_hi_f(h0));
                uint32_t w1 = packbf(v.z - bf_lo_f(h1), v.w - bf_hi_f(h1));
                dh[r * KW + c4 * 2]     = h0;
                dh[r * KW + c4 * 2 + 1] = h1;
                dl[r * KW + c4 * 2]     = w0;
                dl[r * KW + c4 * 2 + 1] = w1;
            }
        }
    }
    __syncthreads();
    uint32_t qa[4][4][4];
#pragma unroll
    for (int a = 0; a < 4; ++a) {
        const uint32_t* base = smw + a * (128 * KW);
#pragma unroll
        for (int s = 0; s < 4; ++s) {
            int w = tg + 8 * s;
            qa[a][s][0] = base[(m_loc)     * KW + w];
            qa[a][s][1] = base[(m_loc + 8) * KW + w];
            qa[a][s][2] = base[(m_loc)     * KW + w + 4];
            qa[a][s][3] = base[(m_loc + 8) * KW + w + 4];
        }
    }
    __syncthreads();     // Q fragments read; smem free for pipeline buffers

    // ---- cp.async tile loader ----
    auto issue_loads = [&](int kt, int buf) {
        const uint32_t dstb = sb + (uint32_t)buf * BUFW * 4;
        const unsigned krow = (unsigned)(bh * NS + kt * TK);
        const unsigned vrow = (unsigned)(bh * 64);
        const unsigned vcol = (unsigned)(kt * 32);
#pragma unroll
        for (int i = 0; i < 12; ++i) {
            const int arr = i >> 1;
            int c = (i & 1) * 256 + tid;          // 0..511
            int row = c >> 3, cq = c & 7;
            uint32_t dst = dstb + (uint32_t)(arr * ABUF + row * KW + cq * 4) * 4;
            const unsigned* src;
            if      (arr == 0) src = &g_k1h[(size_t)(krow + row) * 32 + cq * 4];
            else if (arr == 1) src = &g_k1l[(size_t)(krow + row) * 32 + cq * 4];
            else if (arr == 2) src = &g_k2h[(size_t)(krow + row) * 32 + cq * 4];
            else if (arr == 3) src = &g_k2l[(size_t)(krow + row) * 32 + cq * 4];
            else if (arr == 4) src = &g_vth[(size_t)(vrow + row) * 1024 + vcol + cq * 4];
            else               src = &g_vtl[(size_t)(vrow + row) * 1024 + vcol + cq * 4];
            CP16(dst, src);
        }
        CP_COMMIT();
    };

    issue_loads(0, 0);

    float o[8][4];
#pragma unroll
    for (int j = 0; j < 8; ++j) { o[j][0] = o[j][1] = o[j][2] = o[j][3] = 0.f; }
    float lr0 = 0.f, lr1 = 0.f;
    const float SCL2 = 0.18033688f;   // log2(e)/8

    const unsigned wrow = (unsigned)(bh * NS + qt * TQ + (tid >> 1)) * MWPR + (tid & 1);

    for (int kt = 0; kt < NKT; ++kt) {
        __syncthreads();                    // prev tile smem/smask reads done
        if (kt + 1 < NKT) issue_loads(kt + 1, (kt + 1) & 1);

        // threefry for this tile's mask word (ALU pipe; overlaps in-flight loads)
        smask[tid] = tf_word(wrow + kt * 2);

        if (kt + 1 < NKT) { asm volatile("cp.async.wait_group 1;" ::: "memory"); }
        else              { asm volatile("cp.async.wait_group 0;" ::: "memory"); }
        __syncthreads();                    // tile data + mask words visible

        const uint32_t* bufb = smw + (kt & 1) * BUFW;
        const uint32_t* sK0 = bufb;
        const uint32_t* sK1 = bufb + ABUF;
        const uint32_t* sK2 = bufb + 2 * ABUF;
        const uint32_t* sK3 = bufb + 3 * ABUF;
        const uint32_t* sVh = bufb + 4 * ABUF;
        const uint32_t* sVl = bufb + 5 * ABUF;

        // ---- QK: 6 split passes ----
        float c[8][4];
#pragma unroll
        for (int j = 0; j < 8; ++j) { c[j][0] = c[j][1] = c[j][2] = c[j][3] = 0.f; }
#pragma unroll
        for (int j = 0; j < 8; ++j) {
            const int row = j * 8 + gid;
#pragma unroll
            for (int s = 0; s < 4; ++s) {
                const int w = tg + 8 * s;
                uint32_t b1h0 = sK0[row * KW + w], b1h1 = sK0[row * KW + w + 4];
                uint32_t b1l0 = sK1[row * KW + w], b1l1 = sK1[row * KW + w + 4];
                uint32_t b2h0 = sK2[row * KW + w], b2h1 = sK2[row * KW + w + 4];
                uint32_t b2l0 = sK3[row * KW + w], b2l1 = sK3[row * KW + w + 4];
                mma_bf16(c[j], qa[0][s][0], qa[0][s][1], qa[0][s][2], qa[0][s][3], b1h0, b1h1);
                mma_bf16(c[j], qa[0][s][0], qa[0][s][1], qa[0][s][2], qa[0][s][3], b1l0, b1l1);
                mma_bf16(c[j], qa[1][s][0], qa[1][s][1], qa[1][s][2], qa[1][s][3], b1h0, b1h1);
                mma_bf16(c[j], qa[2][s][0], qa[2][s][1], qa[2][s][2], qa[2][s][3], b2h0, b2h1);
                mma_bf16(c[j], qa[2][s][0], qa[2][s][1], qa[2][s][2], qa[2][s][3], b2l0, b2l1);
                mma_bf16(c[j], qa[3][s][0], qa[3][s][1], qa[3][s][2], qa[3][s][3], b2h0, b2h1);
            }
        }

        // ---- exp2 + unmasked l + dropout-masked numerator ----
        const unsigned w00 = smask[m_loc * 2],       w01 = smask[m_loc * 2 + 1];
        const unsigned w10 = smask[(m_loc + 8) * 2], w11 = smask[(m_loc + 8) * 2 + 1];
#pragma unroll
        for (int j = 0; j < 8; ++j) {
            const int sh = ((j & 3) * 8) + tg * 2;
            const unsigned wm  = (j < 4) ? w00 : w01;
            const unsigned wm8 = (j < 4) ? w10 : w11;
            float p0 = ex2f(c[j][0] * SCL2), p1 = ex2f(c[j][1] * SCL2);
            float p2 = ex2f(c[j][2] * SCL2), p3 = ex2f(c[j][3] * SCL2);
            lr0 += p0 + p1;
            lr1 += p2 + p3;
            c[j][0] = ((wm  >> sh)       & 1u) ? p0 : 0.f;
            c[j][1] = ((wm  >> (sh + 1)) & 1u) ? p1 : 0.f;
            c[j][2] = ((wm8 >> sh)       & 1u) ? p2 : 0.f;
            c[j][3] = ((wm8 >> (sh + 1)) & 1u) ? p3 : 0.f;
        }

        // ---- PV: repack C -> A-frags (hi/lo), 3 split passes ----
#pragma unroll
        for (int s = 0; s < 4; ++s) {
            uint32_t ph[4], pl[4];
            {
                float x, y;
                x = c[2 * s][0];     y = c[2 * s][1];
                ph[0] = packbf(x, y); pl[0] = packbf(x - bf_lo_f(ph[0]), y - bf_hi_f(ph[0]));
                x = c[2 * s][2];     y = c[2 * s][3];
                ph[1] = packbf(x, y); pl[1] = packbf(x - bf_lo_f(ph[1]), y - bf_hi_f(ph[1]));
                x = c[2 * s + 1][0]; y = c[2 * s + 1][1];
                ph[2] = packbf(x, y); pl[2] = packbf(x - bf_lo_f(ph[2]), y - bf_hi_f(ph[2]));
                x = c[2 * s + 1][2]; y = c[2 * s + 1][3];
                ph[3] = packbf(x, y); pl[3] = packbf(x - bf_lo_f(ph[3]), y - bf_hi_f(ph[3]));
            }
#pragma unroll
            for (int j = 0; j < 8; ++j) {
                const int row = j * 8 + gid;
                const int w = tg + 8 * s;
                uint32_t vh0 = sVh[row * KW + w], vh1 = sVh[row * KW + w + 4];
                uint32_t vl0 = sVl[row * KW + w], vl1 = sVl[row * KW + w + 4];
                mma_bf16(o[j], ph[0], ph[1], ph[2], ph[3], vh0, vh1);
                mma_bf16(o[j], ph[0], ph[1], ph[2], ph[3], vl0, vl1);
                mma_bf16(o[j], pl[0], pl[1], pl[2], pl[3], vh0, vh1);
            }
        }
    }

    // ---- reduce l within quad, normalize, store ----
    lr0 += __shfl_xor_sync(0xffffffffu, lr0, 1);
    lr0 += __shfl_xor_sync(0xffffffffu, lr0, 2);
    lr1 += __shfl_xor_sync(0xffffffffu, lr1, 1);
    lr1 += __shfl_xor_sync(0xffffffffu, lr1, 2);
    const float inv0 = 2.0f / lr0;
    const float inv1 = 2.0f / lr1;

    float* ob = out + bh_off + (size_t)(qt * TQ + m_loc) * ND;
#pragma unroll
    for (int j = 0; j < 8; ++j) {
        const int d = j * 8 + tg * 2;
        *(float2*)&ob[d]          = make_float2(o[j][0] * inv0, o[j][1] * inv0);
        *(float2*)&ob[8 * ND + d] = make_float2(o[j][2] * inv1, o[j][3] * inv1);
    }
}

extern "C" void kernel_launch(void* const* d_in, const int* in_sizes, int n_in,
                              void* d_out, int out_size) {
    const float* q1 = (const float*)d_in[0];
    const float* q2 = (const float*)d_in[1];
    const float* k1 = (const float*)d_in[2];
    const float* k2 = (const float*)d_in[3];
    const float* v1 = (const float*)d_in[4];
    const float* v2 = (const float*)d_in[5];
    float* out = (float*)d_out;

    kprep_kernel<<<dim3(4096, 2), 256>>>((const float4*)k1, (const float4*)k2);
    vtrans_kernel<<<dim3(NS / 64, NB * NH), 256>>>(v1, v2);
    const int smem = (2 * BUFW + 256) * (int)sizeof(uint32_t);   // 111,616 B
    cudaFuncSetAttribute(attn_kernel, cudaFuncAttributeMaxDynamicSharedMemorySize, smem);
    attn_kernel<<<dim3(NS / TQ, NB * NH), 256, smem>>>(q1, q2, out);
}